// round 9
// baseline (speedup 1.0000x reference)
#include <cuda_runtime.h>
#include <cuda_bf16.h>

// ShiftingLayer: out[b,d,c] = (1/AMP) * sum_s exp(-(s - center[b,d])^2) * in[b,s,c]
//   center[b,d] = (d+1 + w[b,d]) * (S/D), s = 1..S (1-indexed).
//
// R8 structure (best known: 16 d's/block, 4 serialized d's per thread,
// 6-deep LDG.128 batches, smem-staged weights with INV_AMP folded in).
// R9 change: __launch_bounds__(256,5) -> 51-reg cap, 5 blocks/SM, to raise
// in-flight memory parallelism at the DRAM wall. Live set ~46 regs: no spill.

#define B_ 16
#define S_ 4096
#define C_ 256
#define D_ 1024

constexpr int   DT      = 16;         // d's per block
constexpr int   K_      = 6;          // window rows per d
constexpr int   RAD     = 2;          // floor(c)-RAD .. floor(c)+RAD+3
constexpr float SCALE   = (float)S_ / (float)D_;   // 4.0
constexpr float INV_AMP = 1.0f / 1.772637204826652f;

__global__ __launch_bounds__(256, 5)
void ShiftingLayer_53798760349850_kernel(const float* __restrict__ in,
                                         const float* __restrict__ wts,
                                         float* __restrict__ out) {
    __shared__ float s_w[DT][K_ + 2];   // +2 pad: bank-stagger rows
    __shared__ int   s_ss[DT];

    const int tid = threadIdx.x;
    const int b   = blockIdx.x / (D_ / DT);
    const int d0  = (blockIdx.x % (D_ / DT)) * DT;

    // Precompute windows + weights (INV_AMP folded in): DT*K_=96 threads.
    if (tid < DT * K_) {
        const int j = tid / K_;
        const int k = tid - j * K_;
        const float c = ((float)(d0 + j + 1) + wts[b * D_ + d0 + j]) * SCALE;
        int ss = (int)floorf(c) - RAD;            // 1-indexed window start
        if (ss < 1) ss = 1;
        if (ss > S_ - K_ + 1) ss = S_ - K_ + 1;
        const float diff = (float)(ss + k) - c;
        s_w[j][k] = __expf(-diff * diff) * INV_AMP;
        if (k == 0) s_ss[j] = ss;
    }
    __syncthreads();

    const int cq = tid & 63;            // channel quad (64 per row)
    const int g  = tid >> 6;            // d-group 0..3

    const int qstride = C_ / 4;
    const float4* inb = reinterpret_cast<const float4*>(in) + (b * S_) * qstride + cq;
    float4* outb = reinterpret_cast<float4*>(out) + (b * D_ + d0) * qstride + cq;

#pragma unroll
    for (int jj = 0; jj < 4; jj++) {
        const int j  = g * 4 + jj;
        const int ss = s_ss[j];

        const float4* p = inb + (ss - 1) * qstride;

        // Issue all 6 independent LDG.128 first
        float4 x[K_];
#pragma unroll
        for (int k = 0; k < K_; k++)
            x[k] = p[k * qstride];

        // Broadcast weight reads (overlap with load latency)
        float wk[K_];
#pragma unroll
        for (int k = 0; k < K_; k++)
            wk[k] = s_w[j][k];

        float4 acc = make_float4(0.f, 0.f, 0.f, 0.f);
#pragma unroll
        for (int k = 0; k < K_; k++) {
            acc.x = fmaf(wk[k], x[k].x, acc.x);
            acc.y = fmaf(wk[k], x[k].y, acc.y);
            acc.z = fmaf(wk[k], x[k].z, acc.z);
            acc.w = fmaf(wk[k], x[k].w, acc.w);
        }

        outb[j * qstride] = acc;
    }
}

extern "C" void kernel_launch(void* const* d_in, const int* in_sizes, int n_in,
                              void* d_out, int out_size) {
    const float* in  = (const float*)d_in[0];   // (16, 4096, 256) f32
    const float* wts = (const float*)d_in[1];   // (16, 1024) f32
    float*       out = (float*)d_out;           // (16, 1024, 256) f32

    dim3 grid(B_ * (D_ / DT));   // 1024
    dim3 block(256);
    ShiftingLayer_53798760349850_kernel<<<grid, block>>>(in, wts, out);
}

// round 12
// speedup vs baseline: 1.0380x; 1.0380x over previous
#include <cuda_runtime.h>
#include <cuda_bf16.h>

// ShiftingLayer: out[b,d,c] = (1/AMP) * sum_s exp(-(s - center[b,d])^2) * in[b,s,c]
//   center[b,d] = (d+1 + w[b,d]) * (S/D), s = 1..S (1-indexed).
//
// R8 structure exactly (best known: 16 d's/block, 4 serialized d's per thread,
// 6-deep LDG.128 batches, smem-staged weights with INV_AMP folded in,
// __launch_bounds__(256,4)). R10 change: __stcs streaming output stores so the
// write-once output doesn't evict the input working set from L2 (L2 residency
// across graph replays is what keeps DRAM traffic below compulsory).

#define B_ 16
#define S_ 4096
#define C_ 256
#define D_ 1024

constexpr int   DT      = 16;         // d's per block
constexpr int   K_      = 6;          // window rows per d
constexpr int   RAD     = 2;          // floor(c)-RAD .. floor(c)+RAD+3
constexpr float SCALE   = (float)S_ / (float)D_;   // 4.0
constexpr float INV_AMP = 1.0f / 1.772637204826652f;

__global__ __launch_bounds__(256, 4)
void ShiftingLayer_53798760349850_kernel(const float* __restrict__ in,
                                         const float* __restrict__ wts,
                                         float* __restrict__ out) {
    __shared__ float s_w[DT][K_ + 2];   // +2 pad: bank-stagger rows
    __shared__ int   s_ss[DT];

    const int tid = threadIdx.x;
    const int b   = blockIdx.x / (D_ / DT);
    const int d0  = (blockIdx.x % (D_ / DT)) * DT;

    // Precompute windows + weights (INV_AMP folded in): DT*K_=96 threads.
    if (tid < DT * K_) {
        const int j = tid / K_;
        const int k = tid - j * K_;
        const float c = ((float)(d0 + j + 1) + __ldg(&wts[b * D_ + d0 + j])) * SCALE;
        int ss = (int)floorf(c) - RAD;            // 1-indexed window start
        if (ss < 1) ss = 1;
        if (ss > S_ - K_ + 1) ss = S_ - K_ + 1;
        const float diff = (float)(ss + k) - c;
        s_w[j][k] = __expf(-diff * diff) * INV_AMP;
        if (k == 0) s_ss[j] = ss;
    }
    __syncthreads();

    const int cq = tid & 63;            // channel quad (64 per row)
    const int g  = tid >> 6;            // d-group 0..3

    const int qstride = C_ / 4;
    const float4* inb = reinterpret_cast<const float4*>(in) + (b * S_) * qstride + cq;
    float4* outb = reinterpret_cast<float4*>(out) + (b * D_ + d0) * qstride + cq;

#pragma unroll
    for (int jj = 0; jj < 4; jj++) {
        const int j  = g * 4 + jj;
        const int ss = s_ss[j];

        const float4* p = inb + (ss - 1) * qstride;

        // Issue all 6 independent LDG.128 first
        float4 x[K_];
#pragma unroll
        for (int k = 0; k < K_; k++)
            x[k] = p[k * qstride];

        // Broadcast weight reads (overlap with load latency)
        float wk[K_];
#pragma unroll
        for (int k = 0; k < K_; k++)
            wk[k] = s_w[j][k];

        float4 acc = make_float4(0.f, 0.f, 0.f, 0.f);
#pragma unroll
        for (int k = 0; k < K_; k++) {
            acc.x = fmaf(wk[k], x[k].x, acc.x);
            acc.y = fmaf(wk[k], x[k].y, acc.y);
            acc.z = fmaf(wk[k], x[k].z, acc.z);
            acc.w = fmaf(wk[k], x[k].w, acc.w);
        }

        // Streaming store: write-once data, evict-first in L2.
        __stcs(&outb[j * qstride], acc);
    }
}

extern "C" void kernel_launch(void* const* d_in, const int* in_sizes, int n_in,
                              void* d_out, int out_size) {
    const float* in  = (const float*)d_in[0];   // (16, 4096, 256) f32
    const float* wts = (const float*)d_in[1];   // (16, 1024) f32
    float*       out = (float*)d_out;           // (16, 1024, 256) f32

    dim3 grid(B_ * (D_ / DT));   // 1024
    dim3 block(256);
    ShiftingLayer_53798760349850_kernel<<<grid, block>>>(in, wts, out);
}